// round 16
// baseline (speedup 1.0000x reference)
#include <cuda_runtime.h>
#include <cstdint>

#define NATOM 8192
#define EMAX  131072
#define EPAD  (EMAX + 3 * NATOM)   // CSR padded to multiple-of-4 per atom
#define NW    16
#define NPU   10                   // unique angular comps: 1 + 3 + 6 (sym l=2)
#define NFU   160                  // NPU * NW
#define NORB  128
#define NHID  64

// ---------------- device scratch (no allocs allowed) ----------------
// __device__ globals are zero-initialized; pad slots in g_edge/g_ejd are
// never written -> read as zeros -> contribute exactly 0 to the gather.
__device__ __align__(16)  int   g_count[NATOM];      // self-cleaned by k_scan
__device__ __align__(16)  int   g_offset[NATOM + 1]; // PADDED prefix
__device__ __align__(16)  int   g_cursor[NATOM];
__device__ __align__(16)  int2  g_ejd[EPAD];                 // CSR slot -> {j, dcut}
__device__ __align__(256) float g_edge[(size_t)EPAD * 32];   // CSR-ordered AoS 128B/edge
__device__ __align__(256) float g_WsumA[(size_t)NATOM * NFU];
__device__ __align__(256) float g_WsumB[(size_t)NATOM * NFU];
__device__ __align__(256) float g_coeff[(size_t)NATOM * NW];
__device__ __align__(256) float g_density[(size_t)NATOM * NORB];

__device__ const float* g_rs_p;
__device__ const float* g_inta_p;
__device__ const float* g_par_p;

// packed f32x2 helpers (Blackwell packed FMA; rounding identical to FFMA)
#define FMA2(acc, a, b) \
    asm("fma.rn.f32x2 %0, %1, %2, %0;" : "+l"(acc) : "l"(a), "l"(b))
#define PACK2(out, lo, hi) \
    asm("mov.b64 %0, {%1, %2};" : "=l"(out) : "f"(lo), "f"(hi))
#define UNPACK2(lo, hi, in) \
    asm("mov.b64 {%0, %1}, %2;" : "=f"(lo), "=f"(hi) : "l"(in))

// ------ prep: per-block trio classification + histogram + coeff -----
__global__ void __launch_bounds__(256) k_prep(
        const float* a, const float* b, const float* c,
        const int* __restrict__ neigh, const int* __restrict__ species, int E) {
    __shared__ float mx[3];
    int tid = threadIdx.x;
    if (tid < 96) {
        int w = tid >> 5, lane = tid & 31;
        const float* p = (w == 0) ? a : (w == 1) ? b : c;
        float m = fmaxf(p[lane], p[lane + 32]);
#pragma unroll
        for (int off = 16; off; off >>= 1)
            m = fmaxf(m, __shfl_xor_sync(0xffffffffu, m, off));
        if (lane == 0) mx[w] = m;
    }
    __syncthreads();
    int inta_i = 0;
    if (mx[1] < 0.f) inta_i = 1;
    if (mx[2] < 0.f) inta_i = 2;
    int r0 = (inta_i == 0) ? 1 : 0;
    int r1 = (inta_i == 2) ? 1 : 2;
    int rs_i, pp_i;
    if (mx[r0] > mx[r1]) { rs_i = r0; pp_i = r1; }
    else                 { rs_i = r1; pp_i = r0; }
    const float* ptr[3] = {a, b, c};
    const float* par = ptr[pp_i];
    if (blockIdx.x == 0 && tid == 0) {
        g_inta_p = ptr[inta_i];
        g_rs_p   = ptr[rs_i];
        g_par_p  = par;
    }
    int t = blockIdx.x * 256 + tid;
    if (t < E) {
        int i = neigh[t];
        if ((unsigned)i < NATOM) atomicAdd(&g_count[i], 1);
    }
    if (t < NATOM * NW) {
        int i = t >> 4, k = t & 15;
        g_coeff[t] = par[species[i] * NW + k];
    }
}

// ------ single-block shuffle scan (PADDED counts); self-cleans ------
__global__ void __launch_bounds__(1024) k_scan() {
    int tid = threadIdx.x;
    int lane = tid & 31, wid = tid >> 5;
    int4 c0 = *(const int4*)(g_count + tid * 8);
    int4 c1 = *(const int4*)(g_count + tid * 8 + 4);
    int v[8] = {c0.x, c0.y, c0.z, c0.w, c1.x, c1.y, c1.z, c1.w};
    int s = 0;
#pragma unroll
    for (int u = 0; u < 8; u++) {
        v[u] = (v[u] + 3) & ~3;
        s += v[u];
    }
    int incl = s;
#pragma unroll
    for (int off = 1; off < 32; off <<= 1) {
        int n = __shfl_up_sync(0xffffffffu, incl, off);
        if (lane >= off) incl += n;
    }
    __shared__ int wexcl[32];
    __shared__ int wtot[32];
    if (lane == 31) wtot[wid] = incl;
    __syncthreads();
    if (wid == 0) {
        int t = wtot[lane];
        int ti = t;
#pragma unroll
        for (int off = 1; off < 32; off <<= 1) {
            int n = __shfl_up_sync(0xffffffffu, ti, off);
            if (lane >= off) ti += n;
        }
        wexcl[lane] = ti - t;
    }
    __syncthreads();
    int run = wexcl[wid] + (incl - s);
    int o[8];
#pragma unroll
    for (int u = 0; u < 8; u++) { o[u] = run; run += v[u]; }
    int4 o0 = {o[0], o[1], o[2], o[3]};
    int4 o1 = {o[4], o[5], o[6], o[7]};
    *(int4*)(g_offset + tid * 8) = o0;
    *(int4*)(g_offset + tid * 8 + 4) = o1;
    *(int4*)(g_cursor + tid * 8) = o0;
    *(int4*)(g_cursor + tid * 8 + 4) = o1;
    if (tid == 1023) g_offset[NATOM] = run;
    int4 z = {0, 0, 0, 0};
    *(int4*)(g_count + tid * 8) = z;
    *(int4*)(g_count + tid * 8 + 4) = z;
}

// ------ per-edge geometry, stored DIRECTLY at CSR slot --------------
// row layout (32 floats): [0..1]=0, [2..11]=ang_u[10] (ang_u[0]=dcut,
// [1..3]=dcut*u, [4..9]=dcut*{xx,xy,xz,yy,yz,zz}), [12..15]=0, [16..31]=rad
#define EB 128
__global__ void __launch_bounds__(EB) k_edges(
        const float* __restrict__ cart, const float* __restrict__ shifts,
        const int* __restrict__ species, const int* __restrict__ neigh, int E) {
    __shared__ float st[EB * 33];
    __shared__ int spos[EB];
    int tid = threadIdx.x;
    int e = blockIdx.x * EB + tid;
    float* row = st + tid * 33;
    if (e < E) {
        const float* rs   = g_rs_p;
        const float* inta = g_inta_p;
        int i = neigh[e];
        int j = neigh[E + e];
        float dx = cart[i * 3 + 0] - cart[j * 3 + 0] - shifts[e * 3 + 0];
        float dy = cart[i * 3 + 1] - cart[j * 3 + 1] - shifts[e * 3 + 1];
        float dz = cart[i * 3 + 2] - cart[j * 3 + 2] - shifts[e * 3 + 2];
        float dist = sqrtf(dx * dx + dy * dy + dz * dz);
        int pos = atomicAdd(&g_cursor[i], 1);
        float inv = 1.0f / dist;
        float ux = dx * inv, uy = dy * inv, uz = dz * inv;
        float c = 0.5f * cosf(dist * 0.6283185307179586f) + 0.5f;  // pi/5
        float dcut = c * c;
        int sp = species[j];
        row[0] = 0.f; row[1] = 0.f;
        row[2] = dcut;
        row[3] = dcut * ux; row[4] = dcut * uy; row[5] = dcut * uz;
        row[6] = dcut * ux * ux;  // xx
        row[7] = dcut * ux * uy;  // xy
        row[8] = dcut * ux * uz;  // xz
        row[9] = dcut * uy * uy;  // yy
        row[10] = dcut * uy * uz; // yz
        row[11] = dcut * uz * uz; // zz
        row[12] = 0.f; row[13] = 0.f; row[14] = 0.f; row[15] = 0.f;
#pragma unroll
        for (int k = 0; k < NW; k++) {
            float t = dist - rs[sp * NW + k];
            row[16 + k] = expf(inta[sp * NW + k] * t * t);
        }
        spos[tid] = pos;
        g_ejd[pos] = make_int2(j, __float_as_int(dcut));
    } else {
        spos[tid] = -1;
    }
    __syncthreads();
    int r = tid >> 3, q = tid & 7;
    for (; r < EB; r += 16) {
        int pos = spos[r];
        if (pos >= 0) {
            const float* src = st + r * 33 + q * 4;
            float4 v = {src[0], src[1], src[2], src[3]};
            *(float4*)(g_edge + (size_t)pos * 32 + q * 4) = v;
        }
    }
}

// ---------------- per-atom gather + hyper einsum + density ----------
// 2 atoms per block (128 threads). Gather: two 64-thread groups (40 active
// each). Density: ALL 128 threads, one orbit column each, BOTH atoms per H
// load via packed fma.rn.f32x2 on atom-interleaved features F_pk.
// PASS 0: WsumA = F; PASS 1: WsumB = WsumA + F; PASS 2: no Wsum write.
template <int PASS>
__global__ void __launch_bounds__(128, 6)
k_atom(const float* __restrict__ ef, const float* __restrict__ ef_para,
       const float* __restrict__ hyper, float* __restrict__ dens_final) {
    int tid = threadIdx.x;
    int ga = tid >> 6;                 // atom group 0/1
    int t = tid & 63;
    int i = blockIdx.x * 2 + ga;
    __shared__ float F_pk[NFU * 2];    // [fb] -> (atomA, atomB), 8B pairs
    const float* WsumIn = (PASS == 1) ? g_WsumA : g_WsumB;
    float* WsumOut = (PASS == 0) ? g_WsumA : g_WsumB;
    int start = g_offset[i], end = g_offset[i + 1];

    // ---- gather: 40 of 64 threads accumulate (p=0..9, kq 4-wide) ----
    {
        int p = min(t >> 2, 9);
        int kq = (t & 3) << 2;
        int b = i >> 9;  // A = 512 atoms per batch
        float e0 = ef[b * 3], e1 = ef[b * 3 + 1], e2 = ef[b * 3 + 2];
        float angef;
        if (p == 0) angef = 1.f;
        else if (p < 4) angef = (p == 1) ? e0 : ((p == 2) ? e1 : e2);
        else {
            // unique pairs: 4:xx 5:xy 6:xz 7:yy 8:yz 9:zz
            float ua = (p < 7) ? e0 : ((p < 9) ? e1 : e2);
            float ub = (p == 4) ? e0 : (p == 5) ? e1 : (p == 6) ? e2 :
                       (p == 7) ? e1 : (p == 8) ? e2 : e2;
            angef = ua * ub;
        }
        float4 epr = *(const float4*)(ef_para + kq);
        float ax = angef * epr.x, ay = angef * epr.y;
        float az = angef * epr.z, aw = angef * epr.w;

        int4 nA = {0, 0, 0, 0}, nB = {0, 0, 0, 0};
        if (start < end) {
            nA = *(const int4*)(g_ejd + start);
            nB = *(const int4*)(g_ejd + start + 2);
        }
        for (int s = start; s < end; s += 4) {
            int4 cA = nA, cB = nB;
            int sn = s + 4;
            if (sn < end) {
                nA = *(const int4*)(g_ejd + sn);
                nB = *(const int4*)(g_ejd + sn + 2);
            }
            const float* edb = g_edge + (size_t)s * 32;
#pragma unroll
            for (int u = 0; u < 4; u++) {
                int j = (u == 0) ? cA.x : (u == 1) ? cA.z : (u == 2) ? cB.x : cB.z;
                float dcut = __int_as_float(
                    (u == 0) ? cA.y : (u == 1) ? cA.w : (u == 2) ? cB.y : cB.w);
                const float* ed = edb + u * 32;
                float ang = ed[2 + p];
                float4 rad = *(const float4*)(ed + 16 + kq);
                float4 cf = *(const float4*)(g_coeff + j * NW + kq);
                float ox = ang * rad.x, oy = ang * rad.y;
                float oz = ang * rad.z, ow = ang * rad.w;
                if (PASS > 0) {
                    float4 w = *(const float4*)(WsumIn + (size_t)j * NFU + p * 16 + kq);
                    ox += dcut * w.x; oy += dcut * w.y;
                    oz += dcut * w.z; ow += dcut * w.w;
                }
                ax += cf.x * ox; ay += cf.y * oy;
                az += cf.z * oz; aw += cf.w * ow;
            }
        }
        if (t < 40) {
            int fb = p * 16 + kq;
            // packed shared store: F_pk[fb] = (A, B) at lane ga
            F_pk[(fb + 0) * 2 + ga] = ax;
            F_pk[(fb + 1) * 2 + ga] = ay;
            F_pk[(fb + 2) * 2 + ga] = az;
            F_pk[(fb + 3) * 2 + ga] = aw;
            if (PASS < 2) {
                float4 o = {ax, ay, az, aw};
                if (PASS == 1) {
                    float4 pr = *(const float4*)(WsumIn + (size_t)i * NFU + fb);
                    o.x += pr.x; o.y += pr.y; o.z += pr.z; o.w += pr.w;
                }
                *(float4*)(WsumOut + (size_t)i * NFU + fb) = o;
            }
        }
    }
    __syncthreads();

    // ---- density: ALL 128 threads, one column each, packed over atoms ----
    {
        int m = tid;                      // orbit column
        int i0 = blockIdx.x * 2;
        float* dens_out = (PASS == 2) ? dens_final : g_density;
        const unsigned long long* Fp = (const unsigned long long*)F_pk;
        unsigned long long hw[NPU];
#pragma unroll
        for (int p = 0; p < NPU; p++) hw[p] = 0ull;
#pragma unroll
        for (int kk = 0; kk < NW; kk++) {
            float h0 = hyper[kk * NORB + m];
            float h1 = hyper[NW * NORB + kk * NORB + m];
            float h2 = hyper[2 * NW * NORB + kk * NORB + m];
            unsigned long long h0p, h1p, h2p;
            PACK2(h0p, h0, h0);
            PACK2(h1p, h1, h1);
            PACK2(h2p, h2, h2);
            FMA2(hw[0], Fp[kk], h0p);
#pragma unroll
            for (int q = 1; q < 4; q++) FMA2(hw[q], Fp[q * 16 + kk], h1p);
#pragma unroll
            for (int q = 4; q < 10; q++) FMA2(hw[q], Fp[q * 16 + kk], h2p);
        }
        float dA = 0.f, dB = 0.f;
#pragma unroll
        for (int p = 0; p < NPU; p++) {
            float a, b2;
            UNPACK2(a, b2, hw[p]);
            // l=2 off-diagonal comps (5:xy 6:xz 8:yz) count twice (exact)
            float w = (p == 5 || p == 6 || p == 8) ? 2.f : 1.f;
            dA += w * a * a;
            dB += w * b2 * b2;
        }
        dens_out[(size_t)i0 * NORB + m] = dA;
        dens_out[(size_t)(i0 + 1) * NORB + m] = dB;
    }
}

// ---------------- MLP: coeff += tanh(density@W1+b1)@W2 --------------
__global__ void __launch_bounds__(512)
k_mlp(const float* __restrict__ W1, const float* __restrict__ b1,
      const float* __restrict__ W2) {
    __shared__ float W1T[NHID * 132];   // 33 KB
    __shared__ float dsh[8 * NORB];     // 4 KB
    __shared__ float hsh[8 * NHID];     // 2 KB
    int tid = threadIdx.x;
    int i0 = blockIdx.x * 8;
    for (int idx = tid; idx < NORB * NHID; idx += 512) {
        int k = idx >> 6, h = idx & 63;
        W1T[h * 132 + k] = W1[idx];
    }
    for (int idx = tid; idx < 8 * NORB; idx += 512)
        dsh[idx] = g_density[(size_t)i0 * NORB + idx];
    __syncthreads();
    int a = tid >> 6, h = tid & 63;
    float acc = b1[h];
    const float4* w4 = (const float4*)(W1T + h * 132);
    const float4* d4 = (const float4*)(dsh + a * NORB);
#pragma unroll
    for (int q = 0; q < 32; q++) {
        float4 w = w4[q], d = d4[q];
        acc += w.x * d.x + w.y * d.y + w.z * d.z + w.w * d.w;
    }
    hsh[a * NHID + h] = tanhf(acc);
    __syncthreads();
    if (h < NW) {
        float delta = 0.f;
#pragma unroll
        for (int hh = 0; hh < NHID; hh++)
            delta += hsh[a * NHID + hh] * __ldg(&W2[hh * NW + h]);
        g_coeff[(i0 + a) * NW + h] += delta;
    }
}

// ---------------- launch --------------------------------------------
extern "C" void kernel_launch(void* const* d_in, const int* in_sizes, int n_in,
                              void* d_out, int out_size) {
    const float *cart = 0, *ef = 0, *shifts = 0, *ef_para = 0, *hyper = 0;
    const float *oc_w1 = 0, *oc_b1 = 0, *oc_w2 = 0;
    const int *neigh = 0, *species = 0;   // int32 (JAX x64 disabled)
    const float* trio[3] = {0, 0, 0};
    int ntrio = 0;
    for (int t = 0; t < n_in; t++) {
        int s = in_sizes[t];
        const void* p = d_in[t];
        switch (s) {
            case 24576:  cart    = (const float*)p; break;
            case 48:     ef      = (const float*)p; break;
            case 393216: shifts  = (const float*)p; break;
            case 16:     ef_para = (const float*)p; break;
            case 6144:   hyper   = (const float*)p; break;
            case 16384:  oc_w1   = (const float*)p; break;
            case 128:    oc_b1   = (const float*)p; break;
            case 2048:   oc_w2   = (const float*)p; break;
            case 262144: neigh   = (const int*)p; break;
            case 8192:   species = (const int*)p; break;
            case 64:     if (ntrio < 3) trio[ntrio++] = (const float*)p; break;
            default: break;
        }
    }
    if (!cart || !ef || !shifts || !ef_para || !hyper || !oc_w1 || !oc_b1 ||
        !oc_w2 || !neigh || !species || ntrio != 3) {
        cart    = (const float*)d_in[0];
        ef      = (const float*)d_in[1];
        shifts  = (const float*)d_in[2];
        trio[0] = (const float*)d_in[3];
        trio[1] = (const float*)d_in[4];
        trio[2] = (const float*)d_in[5];
        ef_para = (const float*)d_in[6];
        hyper   = (const float*)d_in[7];
        oc_w1   = (const float*)d_in[8];
        oc_b1   = (const float*)d_in[9];
        oc_w2   = (const float*)d_in[10];
        neigh   = (const int*)d_in[11];
        species = (const int*)d_in[12];
    }
    int E = EMAX;

    k_prep<<<(E + 255) / 256, 256>>>(trio[0], trio[1], trio[2], neigh, species, E);
    k_scan<<<1, 1024>>>();
    k_edges<<<(E + EB - 1) / EB, EB>>>(cart, shifts, species, neigh, E);

    k_atom<0><<<NATOM / 2, 128>>>(ef, ef_para, hyper, nullptr);   // 4th launch (ncu)
    k_mlp<<<NATOM / 8, 512>>>(oc_w1, oc_b1, oc_w2);
    k_atom<1><<<NATOM / 2, 128>>>(ef, ef_para, hyper, nullptr);
    k_mlp<<<NATOM / 8, 512>>>(oc_w1 + NORB * NHID, oc_b1 + NHID, oc_w2 + NHID * NW);
    k_atom<2><<<NATOM / 2, 128>>>(ef, ef_para, hyper, (float*)d_out);
}

// round 17
// speedup vs baseline: 1.0360x; 1.0360x over previous
#include <cuda_runtime.h>
#include <cstdint>

#define NATOM 8192
#define EMAX  131072
#define EPAD  (EMAX + 3 * NATOM)   // CSR padded to multiple-of-4 per atom
#define NW    16
#define NPU   10                   // unique angular comps: 1 + 3 + 6 (sym l=2)
#define NFU   160                  // NPU * NW
#define NORB  128
#define NHID  64

// ---------------- device scratch (no allocs allowed) ----------------
// __device__ globals are zero-initialized; pad slots in g_edge/g_ejd are
// never written -> read as zeros -> contribute exactly 0 to the gather.
__device__ __align__(16)  int   g_count[NATOM];      // self-cleaned by k_scan
__device__ __align__(16)  int   g_offset[NATOM + 1]; // PADDED prefix
__device__ __align__(16)  int   g_cursor[NATOM];
__device__ __align__(16)  int2  g_ejd[EPAD];                 // CSR slot -> {j, dcut}
__device__ __align__(256) float g_edge[(size_t)EPAD * 32];   // CSR-ordered AoS 128B/edge
__device__ __align__(256) float g_WsumA[(size_t)NATOM * NFU];
__device__ __align__(256) float g_WsumB[(size_t)NATOM * NFU];
__device__ __align__(256) float g_coeff[(size_t)NATOM * NW];
__device__ __align__(256) float g_density[(size_t)NATOM * NORB];

__device__ const float* g_rs_p;
__device__ const float* g_inta_p;
__device__ const float* g_par_p;

// ------ prep: per-block trio classification + histogram + coeff -----
__global__ void __launch_bounds__(256) k_prep(
        const float* a, const float* b, const float* c,
        const int* __restrict__ neigh, const int* __restrict__ species, int E) {
    __shared__ float mx[3];
    int tid = threadIdx.x;
    if (tid < 96) {
        int w = tid >> 5, lane = tid & 31;
        const float* p = (w == 0) ? a : (w == 1) ? b : c;
        float m = fmaxf(p[lane], p[lane + 32]);
#pragma unroll
        for (int off = 16; off; off >>= 1)
            m = fmaxf(m, __shfl_xor_sync(0xffffffffu, m, off));
        if (lane == 0) mx[w] = m;
    }
    __syncthreads();
    int inta_i = 0;
    if (mx[1] < 0.f) inta_i = 1;
    if (mx[2] < 0.f) inta_i = 2;
    int r0 = (inta_i == 0) ? 1 : 0;
    int r1 = (inta_i == 2) ? 1 : 2;
    int rs_i, pp_i;
    if (mx[r0] > mx[r1]) { rs_i = r0; pp_i = r1; }
    else                 { rs_i = r1; pp_i = r0; }
    const float* ptr[3] = {a, b, c};
    const float* par = ptr[pp_i];
    if (blockIdx.x == 0 && tid == 0) {
        g_inta_p = ptr[inta_i];
        g_rs_p   = ptr[rs_i];
        g_par_p  = par;
    }
    int t = blockIdx.x * 256 + tid;
    if (t < E) {
        int i = neigh[t];
        if ((unsigned)i < NATOM) atomicAdd(&g_count[i], 1);
    }
    if (t < NATOM * NW) {
        int i = t >> 4, k = t & 15;
        g_coeff[t] = par[species[i] * NW + k];
    }
}

// ------ single-block shuffle scan (PADDED counts); self-cleans ------
__global__ void __launch_bounds__(1024) k_scan() {
    int tid = threadIdx.x;
    int lane = tid & 31, wid = tid >> 5;
    int4 c0 = *(const int4*)(g_count + tid * 8);
    int4 c1 = *(const int4*)(g_count + tid * 8 + 4);
    int v[8] = {c0.x, c0.y, c0.z, c0.w, c1.x, c1.y, c1.z, c1.w};
    int s = 0;
#pragma unroll
    for (int u = 0; u < 8; u++) {
        v[u] = (v[u] + 3) & ~3;
        s += v[u];
    }
    int incl = s;
#pragma unroll
    for (int off = 1; off < 32; off <<= 1) {
        int n = __shfl_up_sync(0xffffffffu, incl, off);
        if (lane >= off) incl += n;
    }
    __shared__ int wexcl[32];
    __shared__ int wtot[32];
    if (lane == 31) wtot[wid] = incl;
    __syncthreads();
    if (wid == 0) {
        int t = wtot[lane];
        int ti = t;
#pragma unroll
        for (int off = 1; off < 32; off <<= 1) {
            int n = __shfl_up_sync(0xffffffffu, ti, off);
            if (lane >= off) ti += n;
        }
        wexcl[lane] = ti - t;
    }
    __syncthreads();
    int run = wexcl[wid] + (incl - s);
    int o[8];
#pragma unroll
    for (int u = 0; u < 8; u++) { o[u] = run; run += v[u]; }
    int4 o0 = {o[0], o[1], o[2], o[3]};
    int4 o1 = {o[4], o[5], o[6], o[7]};
    *(int4*)(g_offset + tid * 8) = o0;
    *(int4*)(g_offset + tid * 8 + 4) = o1;
    *(int4*)(g_cursor + tid * 8) = o0;
    *(int4*)(g_cursor + tid * 8 + 4) = o1;
    if (tid == 1023) g_offset[NATOM] = run;
    int4 z = {0, 0, 0, 0};
    *(int4*)(g_count + tid * 8) = z;
    *(int4*)(g_count + tid * 8 + 4) = z;
}

// ------ per-edge geometry, stored DIRECTLY at CSR slot --------------
// row layout (32 floats): [0..1]=0, [2..11]=ang_u[10] (ang_u[0]=dcut,
// [1..3]=dcut*u, [4..9]=dcut*{xx,xy,xz,yy,yz,zz}), [12..15]=0, [16..31]=rad
#define EB 128
__global__ void __launch_bounds__(EB) k_edges(
        const float* __restrict__ cart, const float* __restrict__ shifts,
        const int* __restrict__ species, const int* __restrict__ neigh, int E) {
    __shared__ float st[EB * 33];
    __shared__ int spos[EB];
    int tid = threadIdx.x;
    int e = blockIdx.x * EB + tid;
    float* row = st + tid * 33;
    if (e < E) {
        const float* rs   = g_rs_p;
        const float* inta = g_inta_p;
        int i = neigh[e];
        int j = neigh[E + e];
        float dx = cart[i * 3 + 0] - cart[j * 3 + 0] - shifts[e * 3 + 0];
        float dy = cart[i * 3 + 1] - cart[j * 3 + 1] - shifts[e * 3 + 1];
        float dz = cart[i * 3 + 2] - cart[j * 3 + 2] - shifts[e * 3 + 2];
        float dist = sqrtf(dx * dx + dy * dy + dz * dz);
        int pos = atomicAdd(&g_cursor[i], 1);
        float inv = 1.0f / dist;
        float ux = dx * inv, uy = dy * inv, uz = dz * inv;
        float c = 0.5f * cosf(dist * 0.6283185307179586f) + 0.5f;  // pi/5
        float dcut = c * c;
        int sp = species[j];
        row[0] = 0.f; row[1] = 0.f;
        row[2] = dcut;
        row[3] = dcut * ux; row[4] = dcut * uy; row[5] = dcut * uz;
        row[6] = dcut * ux * ux;  // xx
        row[7] = dcut * ux * uy;  // xy
        row[8] = dcut * ux * uz;  // xz
        row[9] = dcut * uy * uy;  // yy
        row[10] = dcut * uy * uz; // yz
        row[11] = dcut * uz * uz; // zz
        row[12] = 0.f; row[13] = 0.f; row[14] = 0.f; row[15] = 0.f;
#pragma unroll
        for (int k = 0; k < NW; k++) {
            float t = dist - rs[sp * NW + k];
            row[16 + k] = expf(inta[sp * NW + k] * t * t);
        }
        spos[tid] = pos;
        g_ejd[pos] = make_int2(j, __float_as_int(dcut));
    } else {
        spos[tid] = -1;
    }
    __syncthreads();
    int r = tid >> 3, q = tid & 7;
    for (; r < EB; r += 16) {
        int pos = spos[r];
        if (pos >= 0) {
            const float* src = st + r * 33 + q * 4;
            float4 v = {src[0], src[1], src[2], src[3]};
            *(float4*)(g_edge + (size_t)pos * 32 + q * 4) = v;
        }
    }
}

// ---------------- per-atom gather + hyper einsum + density ----------
// 2 atoms per block (128 threads = two 64-thread groups). Gather: 40 of 64
// threads per group accumulate. Density: threads 0-63 -> atom A, 64-127 ->
// atom B, each thread 2 orbit columns -> per-thread density work HALVED vs
// R15 and runs on all 4 warps. Symmetric l=2 (6 comps, weights {1,2,2,1,2,1}).
// PASS 0: WsumA = F; PASS 1: WsumB = WsumA + F; PASS 2: no Wsum write.
template <int PASS>
__global__ void __launch_bounds__(128, 6)
k_atom(const float* __restrict__ ef, const float* __restrict__ ef_para,
       const float* __restrict__ hyper, float* __restrict__ dens_final) {
    int tid = threadIdx.x;
    int ga = tid >> 6;                 // atom group 0/1
    int t = tid & 63;
    int i = blockIdx.x * 2 + ga;
    __shared__ float F_sh[2 * NFU];
    const float* WsumIn = (PASS == 1) ? g_WsumA : g_WsumB;
    float* WsumOut = (PASS == 0) ? g_WsumA : g_WsumB;
    int start = g_offset[i], end = g_offset[i + 1];

    // ---- gather: 40 of 64 threads accumulate (p=0..9, kq 4-wide) ----
    {
        int p = min(t >> 2, 9);
        int kq = (t & 3) << 2;
        int b = i >> 9;  // A = 512 atoms per batch
        float e0 = ef[b * 3], e1 = ef[b * 3 + 1], e2 = ef[b * 3 + 2];
        float angef;
        if (p == 0) angef = 1.f;
        else if (p < 4) angef = (p == 1) ? e0 : ((p == 2) ? e1 : e2);
        else {
            // unique pairs: 4:xx 5:xy 6:xz 7:yy 8:yz 9:zz
            float ua = (p < 7) ? e0 : ((p < 9) ? e1 : e2);
            float ub = (p == 4) ? e0 : (p == 5) ? e1 : (p == 6) ? e2 :
                       (p == 7) ? e1 : (p == 8) ? e2 : e2;
            angef = ua * ub;
        }
        float4 epr = *(const float4*)(ef_para + kq);
        float ax = angef * epr.x, ay = angef * epr.y;
        float az = angef * epr.z, aw = angef * epr.w;

        int4 nA = {0, 0, 0, 0}, nB = {0, 0, 0, 0};
        if (start < end) {
            nA = *(const int4*)(g_ejd + start);
            nB = *(const int4*)(g_ejd + start + 2);
        }
        for (int s = start; s < end; s += 4) {
            int4 cA = nA, cB = nB;
            int sn = s + 4;
            if (sn < end) {
                nA = *(const int4*)(g_ejd + sn);
                nB = *(const int4*)(g_ejd + sn + 2);
            }
            const float* edb = g_edge + (size_t)s * 32;
#pragma unroll
            for (int u = 0; u < 4; u++) {
                int j = (u == 0) ? cA.x : (u == 1) ? cA.z : (u == 2) ? cB.x : cB.z;
                float dcut = __int_as_float(
                    (u == 0) ? cA.y : (u == 1) ? cA.w : (u == 2) ? cB.y : cB.w);
                const float* ed = edb + u * 32;
                float ang = ed[2 + p];
                float4 rad = *(const float4*)(ed + 16 + kq);
                float4 cf = *(const float4*)(g_coeff + j * NW + kq);
                float ox = ang * rad.x, oy = ang * rad.y;
                float oz = ang * rad.z, ow = ang * rad.w;
                if (PASS > 0) {
                    float4 w = *(const float4*)(WsumIn + (size_t)j * NFU + p * 16 + kq);
                    ox += dcut * w.x; oy += dcut * w.y;
                    oz += dcut * w.z; ow += dcut * w.w;
                }
                ax += cf.x * ox; ay += cf.y * oy;
                az += cf.z * oz; aw += cf.w * ow;
            }
        }
        if (t < 40) {
            int fb = p * 16 + kq;
            float4 v = {ax, ay, az, aw};
            *(float4*)(F_sh + ga * NFU + fb) = v;
            if (PASS < 2) {
                float4 o = v;
                if (PASS == 1) {
                    float4 pr = *(const float4*)(WsumIn + (size_t)i * NFU + fb);
                    o.x += pr.x; o.y += pr.y; o.z += pr.z; o.w += pr.w;
                }
                *(float4*)(WsumOut + (size_t)i * NFU + fb) = o;
            }
        }
    }
    __syncthreads();

    // ---- density: thread group ga handles ITS atom, 2 cols/thread ----
    {
        int m = t * 2;
        float* dens_out = (PASS == 2) ? dens_final : g_density;
        const float* F = F_sh + ga * NFU;
        float dx = 0.f, dy = 0.f;
        // l = 0 (p = 0), weight 1
        {
            float hx = 0.f, hy = 0.f;
#pragma unroll
            for (int kk = 0; kk < NW; kk++) {
                float2 h2 = *(const float2*)(hyper + kk * NORB + m);
                float e = F[kk];
                hx += e * h2.x; hy += e * h2.y;
            }
            dx += hx * hx; dy += hy * hy;
        }
        // l = 1 (p = 1..3), weight 1
        {
            float hx[3] = {0, 0, 0}, hy[3] = {0, 0, 0};
#pragma unroll
            for (int kk = 0; kk < NW; kk++) {
                float2 h2 = *(const float2*)(hyper + NW * NORB + kk * NORB + m);
#pragma unroll
                for (int q = 0; q < 3; q++) {
                    float e = F[(1 + q) * NW + kk];
                    hx[q] += e * h2.x; hy[q] += e * h2.y;
                }
            }
#pragma unroll
            for (int q = 0; q < 3; q++) {
                dx += hx[q] * hx[q]; dy += hy[q] * hy[q];
            }
        }
        // l = 2 unique (p = 4..9), weights {1,2,2,1,2,1}; 2 chunks of 3
#pragma unroll
        for (int g = 0; g < 2; g++) {
            float hx[3] = {0, 0, 0}, hy[3] = {0, 0, 0};
#pragma unroll
            for (int kk = 0; kk < NW; kk++) {
                float2 h2 = *(const float2*)(hyper + 2 * NW * NORB + kk * NORB + m);
#pragma unroll
                for (int q = 0; q < 3; q++) {
                    int pp = 4 + g * 3 + q;
                    float e = F[pp * NW + kk];
                    hx[q] += e * h2.x; hy[q] += e * h2.y;
                }
            }
#pragma unroll
            for (int q = 0; q < 3; q++) {
                int pp = 4 + g * 3 + q;
                float w = (pp == 5 || pp == 6 || pp == 8) ? 2.f : 1.f;
                dx += w * hx[q] * hx[q]; dy += w * hy[q] * hy[q];
            }
        }
        float2 o = {dx, dy};
        *(float2*)(dens_out + (size_t)i * NORB + m) = o;
    }
}

// ---------------- MLP: coeff += tanh(density@W1+b1)@W2 --------------
__global__ void __launch_bounds__(512)
k_mlp(const float* __restrict__ W1, const float* __restrict__ b1,
      const float* __restrict__ W2) {
    __shared__ float W1T[NHID * 132];   // 33 KB
    __shared__ float dsh[8 * NORB];     // 4 KB
    __shared__ float hsh[8 * NHID];     // 2 KB
    int tid = threadIdx.x;
    int i0 = blockIdx.x * 8;
    for (int idx = tid; idx < NORB * NHID; idx += 512) {
        int k = idx >> 6, h = idx & 63;
        W1T[h * 132 + k] = W1[idx];
    }
    for (int idx = tid; idx < 8 * NORB; idx += 512)
        dsh[idx] = g_density[(size_t)i0 * NORB + idx];
    __syncthreads();
    int a = tid >> 6, h = tid & 63;
    float acc = b1[h];
    const float4* w4 = (const float4*)(W1T + h * 132);
    const float4* d4 = (const float4*)(dsh + a * NORB);
#pragma unroll
    for (int q = 0; q < 32; q++) {
        float4 w = w4[q], d = d4[q];
        acc += w.x * d.x + w.y * d.y + w.z * d.z + w.w * d.w;
    }
    hsh[a * NHID + h] = tanhf(acc);
    __syncthreads();
    if (h < NW) {
        float delta = 0.f;
#pragma unroll
        for (int hh = 0; hh < NHID; hh++)
            delta += hsh[a * NHID + hh] * __ldg(&W2[hh * NW + h]);
        g_coeff[(i0 + a) * NW + h] += delta;
    }
}

// ---------------- launch --------------------------------------------
extern "C" void kernel_launch(void* const* d_in, const int* in_sizes, int n_in,
                              void* d_out, int out_size) {
    const float *cart = 0, *ef = 0, *shifts = 0, *ef_para = 0, *hyper = 0;
    const float *oc_w1 = 0, *oc_b1 = 0, *oc_w2 = 0;
    const int *neigh = 0, *species = 0;   // int32 (JAX x64 disabled)
    const float* trio[3] = {0, 0, 0};
    int ntrio = 0;
    for (int t = 0; t < n_in; t++) {
        int s = in_sizes[t];
        const void* p = d_in[t];
        switch (s) {
            case 24576:  cart    = (const float*)p; break;
            case 48:     ef      = (const float*)p; break;
            case 393216: shifts  = (const float*)p; break;
            case 16:     ef_para = (const float*)p; break;
            case 6144:   hyper   = (const float*)p; break;
            case 16384:  oc_w1   = (const float*)p; break;
            case 128:    oc_b1   = (const float*)p; break;
            case 2048:   oc_w2   = (const float*)p; break;
            case 262144: neigh   = (const int*)p; break;
            case 8192:   species = (const int*)p; break;
            case 64:     if (ntrio < 3) trio[ntrio++] = (const float*)p; break;
            default: break;
        }
    }
    if (!cart || !ef || !shifts || !ef_para || !hyper || !oc_w1 || !oc_b1 ||
        !oc_w2 || !neigh || !species || ntrio != 3) {
        cart    = (const float*)d_in[0];
        ef      = (const float*)d_in[1];
        shifts  = (const float*)d_in[2];
        trio[0] = (const float*)d_in[3];
        trio[1] = (const float*)d_in[4];
        trio[2] = (const float*)d_in[5];
        ef_para = (const float*)d_in[6];
        hyper   = (const float*)d_in[7];
        oc_w1   = (const float*)d_in[8];
        oc_b1   = (const float*)d_in[9];
        oc_w2   = (const float*)d_in[10];
        neigh   = (const int*)d_in[11];
        species = (const int*)d_in[12];
    }
    int E = EMAX;

    k_prep<<<(E + 255) / 256, 256>>>(trio[0], trio[1], trio[2], neigh, species, E);
    k_scan<<<1, 1024>>>();
    k_edges<<<(E + EB - 1) / EB, EB>>>(cart, shifts, species, neigh, E);

    k_atom<0><<<NATOM / 2, 128>>>(ef, ef_para, hyper, nullptr);   // 4th launch (ncu)
    k_mlp<<<NATOM / 8, 512>>>(oc_w1, oc_b1, oc_w2);
    k_atom<1><<<NATOM / 2, 128>>>(ef, ef_para, hyper, nullptr);
    k_mlp<<<NATOM / 8, 512>>>(oc_w1 + NORB * NHID, oc_b1 + NHID, oc_w2 + NHID * NW);
    k_atom<2><<<NATOM / 2, 128>>>(ef, ef_para, hyper, (float*)d_out);
}